// round 7
// baseline (speedup 1.0000x reference)
#include <cuda_runtime.h>
#include <cstdint>

#define NQ 4
#define NL 6
#define NC 10
#define DIM 512
#define HPI_F 1.57079632679489661923f

#define THREADS 128
#define ROWS 128
#define CHUNK_ROWS 8
#define CHUNK_FLOATS (CHUNK_ROWS * DIM)          // 4096
#define CHUNK_BYTES  (CHUNK_FLOATS * 4)          // 16384
#define NSTAGE 3
#define NCHUNK (ROWS / CHUNK_ROWS)               // 16

// dynamic smem layout (bytes)
#define OFF_RING  0
#define RING_BYTES (NSTAGE * CHUNK_BYTES)        // 49152
#define OFF_SPRE  (OFF_RING + RING_BYTES)        // 49152 (2048 B)
#define OFF_SU    (OFF_SPRE + 2048)              // 51200 (2048 B)
#define OFF_SG    (OFF_SU + 2048)                // 53248 (768 B)
#define OFF_MBAR  (OFF_SG + 768)                 // 54016 (48 B)
#define SMEM_TOTAL (OFF_MBAR + 64)               // 54080

typedef unsigned long long ull;

__device__ __forceinline__ void fma2(ull& d, ull a, ull b, ull c) {
    asm("fma.rn.f32x2 %0, %1, %2, %3;" : "=l"(d) : "l"(a), "l"(b), "l"(c));
}
__device__ __forceinline__ ull pack2(float lo, float hi) {
    ull r;
    asm("mov.b64 %0, {%1, %2};" : "=l"(r) : "r"(__float_as_uint(lo)), "r"(__float_as_uint(hi)));
    return r;
}
__device__ __forceinline__ void unpack2(ull v, float& lo, float& hi) {
    unsigned int a, b;
    asm("mov.b64 {%0, %1}, %2;" : "=r"(a), "=r"(b) : "l"(v));
    lo = __uint_as_float(a); hi = __uint_as_float(b);
}
__device__ __forceinline__ uint32_t smem_u32(const void* p) {
    uint32_t a;
    asm("{ .reg .u64 t; cvta.to.shared.u64 t, %1; cvt.u32.u64 %0, t; }" : "=r"(a) : "l"(p));
    return a;
}
__device__ __forceinline__ void mbar_init(uint32_t addr, uint32_t cnt) {
    asm volatile("mbarrier.init.shared.b64 [%0], %1;" :: "r"(addr), "r"(cnt) : "memory");
}
__device__ __forceinline__ void mbar_expect_tx(uint32_t addr, uint32_t bytes) {
    asm volatile("mbarrier.arrive.expect_tx.shared.b64 _, [%0], %1;" :: "r"(addr), "r"(bytes) : "memory");
}
__device__ __forceinline__ void mbar_arrive(uint32_t addr) {
    asm volatile("mbarrier.arrive.shared.b64 _, [%0];" :: "r"(addr) : "memory");
}
__device__ __forceinline__ void mbar_wait(uint32_t addr, uint32_t parity) {
    asm volatile(
        "{\n\t.reg .pred P;\n\t"
        "LW_%=:\n\t"
        "mbarrier.try_wait.parity.acquire.cta.shared::cta.b64 P, [%0], %1, 0x989680;\n\t"
        "@P bra LD_%=;\n\t"
        "bra.uni LW_%=;\n\t"
        "LD_%=:\n\t}"
        :: "r"(addr), "r"(parity) : "memory");
}
__device__ __forceinline__ void bulk_copy_g2s(uint32_t dst, const void* src,
                                              uint32_t bytes, uint32_t mbar) {
    asm volatile(
        "cp.async.bulk.shared::cta.global.mbarrier::complete_tx::bytes [%0], [%1], %2, [%3];"
        :: "r"(dst), "l"(src), "r"(bytes), "r"(mbar) : "memory");
}

__global__ __launch_bounds__(THREADS, 4) void vqc_fused_kernel(
    const float* __restrict__ x,
    const float* __restrict__ Wpre,
    const float* __restrict__ bpre,
    const float* __restrict__ qw,
    const float* __restrict__ Wpost,
    const float* __restrict__ bpost,
    float* __restrict__ out)
{
    extern __shared__ char dynsmem[];
    float*  ring = (float*)(dynsmem + OFF_RING);
    float4* spre = (float4*)(dynsmem + OFF_SPRE);
    float2* sU   = (float2*)(dynsmem + OFF_SU);
    float (*sg)[8] = (float(*)[8])(dynsmem + OFF_SG);

    const uint32_t mb_base = smem_u32(dynsmem + OFF_MBAR);
    // full[s] = mb_base + s*8 ; empty[s] = mb_base + 24 + s*8

    const int tid  = threadIdx.x;
    const int lane = tid & 31;
    const int warp = tid >> 5;
    const int row0 = blockIdx.x * ROWS;

    // ---- W_pre into registers ----
    const float4* W4 = (const float4*)Wpre;   // [4][128] float4
    float4 wr[4][4];
#pragma unroll
    for (int w = 0; w < 4; w++)
#pragma unroll
        for (int jj = 0; jj < 4; jj++)
            wr[w][jj] = W4[w * 128 + jj * 32 + lane];

    // ---- gate coefficients + mbarrier init ----
    if (tid < 24) {
        float phi = qw[tid * 3 + 0];
        float th  = qw[tid * 3 + 1];
        float om  = qw[tid * 3 + 2];
        float st, ct; sincosf(0.5f * th, &st, &ct);
        float sa, ca; sincosf(0.5f * (phi + om), &sa, &ca);
        float sb, cb; sincosf(0.5f * (phi - om), &sb, &cb);
        sg[tid][0] =  ca * ct;  sg[tid][1] = -sa * ct;
        sg[tid][2] = -cb * st;  sg[tid][3] = -sb * st;
        sg[tid][4] =  cb * st;  sg[tid][5] = -sb * st;
        sg[tid][6] =  ca * ct;  sg[tid][7] =  sa * ct;
    }
    if (tid == 0) {
#pragma unroll
        for (int s = 0; s < NSTAGE; s++) {
            mbar_init(mb_base + s * 8, 1);            // full: tx-based
            mbar_init(mb_base + 24 + s * 8, THREADS); // empty: all threads arrive
        }
    }
    __syncthreads();

    // ---- prologue: issue first NSTAGE chunk loads ----
    const char* xbase = (const char*)(x + (size_t)row0 * DIM);
    const uint32_t ring_base = smem_u32(ring);
    if (tid == 0) {
#pragma unroll
        for (int k = 0; k < NSTAGE; k++) {
            mbar_expect_tx(mb_base + k * 8, CHUNK_BYTES);
            bulk_copy_g2s(ring_base + k * CHUNK_BYTES,
                          xbase + (size_t)k * CHUNK_BYTES,
                          CHUNK_BYTES, mb_base + k * 8);
        }
    }

    // ---- Phase 0: build U (each warp: 2 passes x 2 columns) ----
#pragma unroll
    for (int p = 0; p < 2; p++) {
        int i = lane & 15;
        int j = warp * 4 + p * 2 + (lane >> 4);
        float re = (i == j) ? 1.0f : 0.0f;
        float im = 0.0f;
#pragma unroll
        for (int l = 0; l < NL; l++) {
#pragma unroll
            for (int w = 0; w < NQ; w++) {
                const float* g = sg[l * NQ + w];
                int m = 8 >> w;
                float pre_ = __shfl_xor_sync(0xffffffffu, re, m);
                float pim  = __shfl_xor_sync(0xffffffffu, im, m);
                bool low = (i & m) == 0;
                float orr = low ? g[0] : g[6];
                float oii = low ? g[1] : g[7];
                float crr = low ? g[2] : g[4];
                float cii = low ? g[3] : g[5];
                float nre = orr * re - oii * im + crr * pre_ - cii * pim;
                float nim = orr * im + oii * re + crr * pim + cii * pre_;
                re = nre; im = nim;
            }
            int r = l % (NQ - 1) + 1;
#pragma unroll
            for (int w = 0; w < NQ; w++) {
                int cmask = 8 >> w;
                int tmask = 8 >> ((w + r) & 3);
                int src_i = (i & cmask) ? (i ^ tmask) : i;
                int srcLane = (lane & 16) | src_i;
                re = __shfl_sync(0xffffffffu, re, srcLane);
                im = __shfl_sync(0xffffffffu, im, srcLane);
            }
        }
        sU[j * 16 + i] = make_float2(re, im);
    }

    // ---- Phase 1: pipelined GEMV from smem ring; 2 rows per warp per chunk ----
    for (int k = 0; k < NCHUNK; k++) {
        int stage = k % NSTAGE;
        uint32_t par = (uint32_t)((k / NSTAGE) & 1);
        mbar_wait(mb_base + stage * 8, par);

        const float4* xr0 = (const float4*)(ring + stage * CHUNK_FLOATS + (warp * 2 + 0) * DIM);
        const float4* xr1 = (const float4*)(ring + stage * CHUNK_FLOATS + (warp * 2 + 1) * DIM);
        float4 xv0[4], xv1[4];
#pragma unroll
        for (int jj = 0; jj < 4; jj++) { xv0[jj] = xr0[jj * 32 + lane]; xv1[jj] = xr1[jj * 32 + lane]; }

        float a0[4] = {0.f, 0.f, 0.f, 0.f};
        float a1[4] = {0.f, 0.f, 0.f, 0.f};
#pragma unroll
        for (int jj = 0; jj < 4; jj++) {
#pragma unroll
            for (int w = 0; w < 4; w++) {
                a0[w] = fmaf(xv0[jj].x, wr[w][jj].x, a0[w]);
                a0[w] = fmaf(xv0[jj].y, wr[w][jj].y, a0[w]);
                a0[w] = fmaf(xv0[jj].z, wr[w][jj].z, a0[w]);
                a0[w] = fmaf(xv0[jj].w, wr[w][jj].w, a0[w]);
                a1[w] = fmaf(xv1[jj].x, wr[w][jj].x, a1[w]);
                a1[w] = fmaf(xv1[jj].y, wr[w][jj].y, a1[w]);
                a1[w] = fmaf(xv1[jj].z, wr[w][jj].z, a1[w]);
                a1[w] = fmaf(xv1[jj].w, wr[w][jj].w, a1[w]);
            }
        }
        // full reduce (both rows interleaved so the shfl chains overlap)
#pragma unroll
        for (int off = 16; off > 0; off >>= 1) {
#pragma unroll
            for (int w = 0; w < 4; w++) {
                a0[w] += __shfl_xor_sync(0xffffffffu, a0[w], off);
                a1[w] += __shfl_xor_sync(0xffffffffu, a1[w], off);
            }
        }
        if (lane == 0) {
            spre[k * 8 + warp * 2 + 0] = make_float4(a0[0], a0[1], a0[2], a0[3]);
            spre[k * 8 + warp * 2 + 1] = make_float4(a1[0], a1[1], a1[2], a1[3]);
        }
        mbar_arrive(mb_base + 24 + stage * 8);

        // refill this stage with chunk k+NSTAGE
        int kn = k + NSTAGE;
        if (tid == 0 && kn < NCHUNK) {
            mbar_wait(mb_base + 24 + stage * 8, par);   // consumers drained
            mbar_expect_tx(mb_base + stage * 8, CHUNK_BYTES);
            bulk_copy_g2s(ring_base + stage * CHUNK_BYTES,
                          xbase + (size_t)kn * CHUNK_BYTES,
                          CHUNK_BYTES, mb_base + stage * 8);
        }
    }
    __syncthreads();

    // ---- Phase 2: thread-per-row quantum ----
    float4 pr = spre[tid];
    float pv[4] = {pr.x + bpre[0], pr.y + bpre[1], pr.z + bpre[2], pr.w + bpre[3]};

    float cw[4], sw[4];
#pragma unroll
    for (int w = 0; w < 4; w++) {
        float e = __expf(2.0f * pv[w]);
        float t = 1.0f - __fdividef(2.0f, e + 1.0f);   // tanh
        float h = HPI_F * t;
        sw[w] = __sinf(h);
        cw[w] = __cosf(h);
    }

    float p01[4], p23[4], v[16];
    p01[0] = cw[0] * cw[1]; p01[1] = cw[0] * sw[1];
    p01[2] = sw[0] * cw[1]; p01[3] = sw[0] * sw[1];
    p23[0] = cw[2] * cw[3]; p23[1] = cw[2] * sw[3];
    p23[2] = sw[2] * cw[3]; p23[3] = sw[2] * sw[3];
#pragma unroll
    for (int a = 0; a < 4; a++)
#pragma unroll
        for (int b = 0; b < 4; b++)
            v[a * 4 + b] = p01[a] * p23[b];

    ull acc64[16];
#pragma unroll
    for (int i = 0; i < 16; i++) acc64[i] = 0ull;
    const ull* sU64 = (const ull*)sU;
#pragma unroll
    for (int jcol = 0; jcol < 16; jcol++) {
        ull vj2 = pack2(v[jcol], v[jcol]);
#pragma unroll
        for (int i = 0; i < 16; i++)
            fma2(acc64[i], sU64[jcol * 16 + i], vj2, acc64[i]);
    }

    float pb[16];
#pragma unroll
    for (int i = 0; i < 16; i++) {
        float re, im; unpack2(acc64[i], re, im);
        pb[i] = re * re + im * im;
    }

    float q[4];
#pragma unroll
    for (int w = 0; w < 4; w++) {
        int m = 8 >> w;
        float s = 0.0f;
#pragma unroll
        for (int i = 0; i < 16; i++) s += (i & m) ? -pb[i] : pb[i];
        q[w] = s;
    }

    float res[NC];
#pragma unroll
    for (int c = 0; c < NC; c++) {
        float o = bpost[c];
#pragma unroll
        for (int w = 0; w < 4; w++) o = fmaf(q[w], Wpost[c * 4 + w], o);
        res[c] = o;
    }

    // stage outputs in (now-dead) ring space for coalesced stores
    __syncthreads();
    float* souts = ring;
#pragma unroll
    for (int c = 0; c < NC; c++) souts[tid * NC + c] = res[c];
    __syncthreads();

    size_t obase = (size_t)row0 * NC;
    for (int i = tid; i < ROWS * NC; i += THREADS)
        out[obase + i] = souts[i];
}

// ---------------------------------------------------------------------------
extern "C" void kernel_launch(void* const* d_in, const int* in_sizes, int n_in,
                              void* d_out, int out_size) {
    const float* x     = (const float*)d_in[0];
    const float* Wpre  = (const float*)d_in[1];
    const float* bpre  = (const float*)d_in[2];
    const float* qw    = (const float*)d_in[3];
    const float* Wpost = (const float*)d_in[4];
    const float* bpost = (const float*)d_in[5];
    float* out = (float*)d_out;

    static bool attr_set = false;
    if (!attr_set) {
        cudaFuncSetAttribute(vqc_fused_kernel,
                             cudaFuncAttributeMaxDynamicSharedMemorySize, SMEM_TOTAL);
        attr_set = true;
    }

    int B = in_sizes[0] / DIM;   // 65536
    vqc_fused_kernel<<<B / ROWS, THREADS, SMEM_TOTAL>>>(
        x, Wpre, bpre, qw, Wpost, bpost, out);
}

// round 8
// speedup vs baseline: 2.6506x; 2.6506x over previous
#include <cuda_runtime.h>
#include <cstdint>

#define NQ 4
#define NL 6
#define NC 10
#define DIM 512
#define HPI_F 1.57079632679489661923f

#define THREADS 128
#define ROWS 128   // rows per block == THREADS (thread-per-row in phase 2)

typedef unsigned long long ull;

__device__ __forceinline__ void fma2(ull& d, ull a, ull b, ull c) {
    asm("fma.rn.f32x2 %0, %1, %2, %3;" : "=l"(d) : "l"(a), "l"(b), "l"(c));
}
__device__ __forceinline__ ull pack2(float lo, float hi) {
    ull r;
    asm("mov.b64 %0, {%1, %2};" : "=l"(r) : "r"(__float_as_uint(lo)), "r"(__float_as_uint(hi)));
    return r;
}
__device__ __forceinline__ void unpack2(ull v, float& lo, float& hi) {
    unsigned int a, b;
    asm("mov.b64 {%0, %1}, %2;" : "=r"(a), "=r"(b) : "l"(v));
    lo = __uint_as_float(a); hi = __uint_as_float(b);
}
__device__ __forceinline__ void prefetch_l2(const void* p, uint32_t bytes) {
    asm volatile("cp.async.bulk.prefetch.L2.global [%0], %1;" :: "l"(p), "r"(bytes));
}

// ---------------------------------------------------------------------------
// Fused kernel (round-6 structure) + rolling L2 bulk prefetch.
// Phase 0: 4 warps build U; each warp evolves 4 basis columns (2 passes).
// Phase 1: warp-per-32-rows GEMV, W_pre in registers, depth-2 row prefetch,
//          rolling 8KB L2 prefetch at distance 8 rows,
//          2-level shfl reduce -> 8 partials/row in smem.
// Phase 2: thread-per-row quantum net + post linear, coalesced output.
// ---------------------------------------------------------------------------
__global__ __launch_bounds__(THREADS, 4) void vqc_fused_kernel(
    const float* __restrict__ x,
    const float* __restrict__ Wpre,
    const float* __restrict__ bpre,
    const float* __restrict__ qw,
    const float* __restrict__ Wpost,
    const float* __restrict__ bpost,
    float* __restrict__ out)
{
    __shared__ float  sg[24][8];
    __shared__ float2 sU[256];              // column-major [j][i]
    __shared__ float4 spart[ROWS * 8];      // 16KB partials
    __shared__ float  souts[ROWS * NC];     // 5KB

    const int tid  = threadIdx.x;
    const int lane = tid & 31;
    const int warp = tid >> 5;
    const int row0 = blockIdx.x * ROWS;
    const int wrow0 = row0 + warp * 32;

    // ---- prologue: L2 prefetch rows 1..8 of this warp's strip, then
    //      first-row register prefetch, all before the U chain ----
    if (lane == 0) {
        const char* pb = (const char*)(x + (size_t)(wrow0 + 1) * DIM);
        prefetch_l2(pb, 8192);            // rows 1-4
        prefetch_l2(pb + 8192, 8192);     // rows 5-8
    }
    const float4* x4 = (const float4*)x;
    float4 xv[4];
    {
        size_t base = (size_t)wrow0 * 128;
#pragma unroll
        for (int jj = 0; jj < 4; jj++) xv[jj] = x4[base + jj * 32 + lane];
    }
    // W_pre into registers
    const float4* W4 = (const float4*)Wpre;   // [4][128] float4
    float4 wr[4][4];
#pragma unroll
    for (int w = 0; w < 4; w++)
#pragma unroll
        for (int jj = 0; jj < 4; jj++)
            wr[w][jj] = W4[w * 128 + jj * 32 + lane];

    // gate coefficients
    if (tid < 24) {
        float phi = qw[tid * 3 + 0];
        float th  = qw[tid * 3 + 1];
        float om  = qw[tid * 3 + 2];
        float st, ct; sincosf(0.5f * th, &st, &ct);
        float sa, ca; sincosf(0.5f * (phi + om), &sa, &ca);
        float sb, cb; sincosf(0.5f * (phi - om), &sb, &cb);
        sg[tid][0] =  ca * ct;  sg[tid][1] = -sa * ct;   // g00
        sg[tid][2] = -cb * st;  sg[tid][3] = -sb * st;   // g01
        sg[tid][4] =  cb * st;  sg[tid][5] = -sb * st;   // g10
        sg[tid][6] =  ca * ct;  sg[tid][7] =  sa * ct;   // g11
    }
    __syncthreads();

    // ---- Phase 0: build U (each warp: 2 passes x 2 columns) ----
#pragma unroll
    for (int p = 0; p < 2; p++) {
        int i = lane & 15;
        int j = warp * 4 + p * 2 + (lane >> 4);
        float re = (i == j) ? 1.0f : 0.0f;
        float im = 0.0f;
#pragma unroll
        for (int l = 0; l < NL; l++) {
#pragma unroll
            for (int w = 0; w < NQ; w++) {
                const float* g = sg[l * NQ + w];
                int m = 8 >> w;
                float pre_ = __shfl_xor_sync(0xffffffffu, re, m);
                float pim  = __shfl_xor_sync(0xffffffffu, im, m);
                bool low = (i & m) == 0;
                float orr = low ? g[0] : g[6];
                float oii = low ? g[1] : g[7];
                float crr = low ? g[2] : g[4];
                float cii = low ? g[3] : g[5];
                float nre = orr * re - oii * im + crr * pre_ - cii * pim;
                float nim = orr * im + oii * re + crr * pim + cii * pre_;
                re = nre; im = nim;
            }
            int r = l % (NQ - 1) + 1;
#pragma unroll
            for (int w = 0; w < NQ; w++) {
                int cmask = 8 >> w;
                int tmask = 8 >> ((w + r) & 3);
                int src_i = (i & cmask) ? (i ^ tmask) : i;
                int srcLane = (lane & 16) | src_i;
                re = __shfl_sync(0xffffffffu, re, srcLane);
                im = __shfl_sync(0xffffffffu, im, srcLane);
            }
        }
        sU[j * 16 + i] = make_float2(re, im);
    }

    // ---- Phase 1: GEMV over 32 rows, depth-2 reg prefetch + L2 prefetch ----
#pragma unroll 4
    for (int rr = 0; rr < 32; rr++) {
        // rolling L2 prefetch: every 4 rows, fetch 4 rows (8KB) at distance 8
        if ((rr & 3) == 0 && (rr + 8) < 32 && lane == 0) {
            const char* pb = (const char*)(x + (size_t)(wrow0 + rr + 9) * DIM);
            prefetch_l2(pb, 8192);
        }
        float4 nx[4];
        if (rr + 1 < 32) {
            size_t base = (size_t)(wrow0 + rr + 1) * 128;
#pragma unroll
            for (int jj = 0; jj < 4; jj++) nx[jj] = x4[base + jj * 32 + lane];
        }
        float acc[4] = {0.f, 0.f, 0.f, 0.f};
#pragma unroll
        for (int jj = 0; jj < 4; jj++) {
#pragma unroll
            for (int w = 0; w < 4; w++) {
                acc[w] = fmaf(xv[jj].x, wr[w][jj].x, acc[w]);
                acc[w] = fmaf(xv[jj].y, wr[w][jj].y, acc[w]);
                acc[w] = fmaf(xv[jj].z, wr[w][jj].z, acc[w]);
                acc[w] = fmaf(xv[jj].w, wr[w][jj].w, acc[w]);
            }
        }
#pragma unroll
        for (int w = 0; w < 4; w++) {
            acc[w] += __shfl_xor_sync(0xffffffffu, acc[w], 16);
            acc[w] += __shfl_xor_sync(0xffffffffu, acc[w], 8);
        }
        if (lane < 8) {
            int lrow = warp * 32 + rr;
            spart[lrow * 8 + lane] = make_float4(acc[0], acc[1], acc[2], acc[3]);
        }
#pragma unroll
        for (int jj = 0; jj < 4; jj++) xv[jj] = nx[jj];
    }
    __syncthreads();

    // ---- Phase 2: thread-per-row quantum ----
    float4 pre4 = make_float4(bpre[0], bpre[1], bpre[2], bpre[3]);
#pragma unroll
    for (int k = 0; k < 8; k++) {
        float4 p = spart[tid * 8 + ((tid + k) & 7)];   // bank-swizzled
        pre4.x += p.x; pre4.y += p.y; pre4.z += p.z; pre4.w += p.w;
    }

    float cw[4], sw[4];
    {
        float pv[4] = {pre4.x, pre4.y, pre4.z, pre4.w};
#pragma unroll
        for (int w = 0; w < 4; w++) {
            float e = __expf(2.0f * pv[w]);
            float t = 1.0f - __fdividef(2.0f, e + 1.0f);   // tanh
            float h = HPI_F * t;
            sw[w] = __sinf(h);
            cw[w] = __cosf(h);
        }
    }

    float p01[4], p23[4], v[16];
    p01[0] = cw[0] * cw[1]; p01[1] = cw[0] * sw[1];
    p01[2] = sw[0] * cw[1]; p01[3] = sw[0] * sw[1];
    p23[0] = cw[2] * cw[3]; p23[1] = cw[2] * sw[3];
    p23[2] = sw[2] * cw[3]; p23[3] = sw[2] * sw[3];
#pragma unroll
    for (int a = 0; a < 4; a++)
#pragma unroll
        for (int b = 0; b < 4; b++)
            v[a * 4 + b] = p01[a] * p23[b];

    ull acc64[16];
#pragma unroll
    for (int i = 0; i < 16; i++) acc64[i] = 0ull;
    const ull* sU64 = (const ull*)sU;
#pragma unroll
    for (int jcol = 0; jcol < 16; jcol++) {
        ull vj2 = pack2(v[jcol], v[jcol]);
#pragma unroll
        for (int i = 0; i < 16; i++)
            fma2(acc64[i], sU64[jcol * 16 + i], vj2, acc64[i]);
    }

    float pb[16];
#pragma unroll
    for (int i = 0; i < 16; i++) {
        float re, im; unpack2(acc64[i], re, im);
        pb[i] = re * re + im * im;
    }

    float q[4];
#pragma unroll
    for (int w = 0; w < 4; w++) {
        int m = 8 >> w;
        float s = 0.0f;
#pragma unroll
        for (int i = 0; i < 16; i++) s += (i & m) ? -pb[i] : pb[i];
        q[w] = s;
    }

#pragma unroll
    for (int c = 0; c < NC; c++) {
        float o = bpost[c];
#pragma unroll
        for (int w = 0; w < 4; w++) o = fmaf(q[w], Wpost[c * 4 + w], o);
        souts[tid * NC + c] = o;
    }
    __syncthreads();

    size_t obase = (size_t)row0 * NC;
    for (int i = tid; i < ROWS * NC; i += THREADS)
        out[obase + i] = souts[i];
}

// ---------------------------------------------------------------------------
extern "C" void kernel_launch(void* const* d_in, const int* in_sizes, int n_in,
                              void* d_out, int out_size) {
    const float* x     = (const float*)d_in[0];
    const float* Wpre  = (const float*)d_in[1];
    const float* bpre  = (const float*)d_in[2];
    const float* qw    = (const float*)d_in[3];
    const float* Wpost = (const float*)d_in[4];
    const float* bpost = (const float*)d_in[5];
    float* out = (float*)d_out;

    int B = in_sizes[0] / DIM;   // 65536
    vqc_fused_kernel<<<B / ROWS, THREADS>>>(x, Wpre, bpre, qw, Wpost, bpost, out);
}